// round 11
// baseline (speedup 1.0000x reference)
#include <cuda_runtime.h>
#include <cuda_fp16.h>
#include <math.h>

#define Bn 1024
#define Dn 512
#define Vn 128
#define Tn 201
#define LSCALE 2048.0f
#define LINV   (1.0f / 2048.0f)

// ---------------- device scratch ----------------
__device__ float  g_h[Bn * Dn];            // h_t (read by final standalone logits)
__device__ float  g_c[Bn * Dn];
__device__ float  g_ctx[Bn * Dn];
__device__ __half g_Ah[2][Bn * Dn];        // ping-pong hx hi-limb
__device__ __half g_Al[2][Bn * Dn];        // ping-pong hx lo-limb (x2048)
__device__ __half g_Bh[4 * Dn * Dn];       // W_hh hi-limb [2048x512]
__device__ __half g_Bl[4 * Dn * Dn];       // W_hh lo-limb (x2048)
__device__ __half g_Ph[Vn * Dn];           // proj_w hi-limb [128x512]
__device__ __half g_Pl[Vn * Dn];           // proj_w lo-limb (x2048)
__device__ float  g_E2[Vn * 4 * Dn];       // embed @ W_ih^T + b_ih + b_hh
__device__ float  g_pwT[Dn * Vn];          // proj_w transposed [K][V] (final logits)
__device__ float  g_CP[Bn * Vn];           // ctx @ proj_w^T  (time-invariant)
__device__ int    g_token[Bn];
__device__ int    g_done;                  // cumulative finished logits blocks

__device__ __forceinline__ float sigexact(float x) {
    return 1.f / (1.f + expf(-x));
}
// scaled split: lo limb premultiplied by 2048 (kept normal in f16; undo in epilogue)
__device__ __forceinline__ void splitf(float x, __half& hi, __half& lo) {
    hi = __float2half_rn(x);
    lo = __float2half_rn((x - __half2float(hi)) * LSCALE);
}

// ---------------- mma / ldmatrix / cp.async wrappers ----------------
__device__ __forceinline__ void mma16816(float* c, const unsigned* a, const unsigned* b) {
    asm volatile(
        "mma.sync.aligned.m16n8k16.row.col.f32.f16.f16.f32 "
        "{%0,%1,%2,%3}, {%4,%5,%6,%7}, {%8,%9}, {%0,%1,%2,%3};"
        : "+f"(c[0]), "+f"(c[1]), "+f"(c[2]), "+f"(c[3])
        : "r"(a[0]), "r"(a[1]), "r"(a[2]), "r"(a[3]), "r"(b[0]), "r"(b[1]));
}
// fp16-accumulator variant (2x rate on the tensor pipe) for scaled correction terms
__device__ __forceinline__ void mma16816h(unsigned* c, const unsigned* a, const unsigned* b) {
    asm volatile(
        "mma.sync.aligned.m16n8k16.row.col.f16.f16.f16.f16 "
        "{%0,%1}, {%2,%3,%4,%5}, {%6,%7}, {%0,%1};"
        : "+r"(c[0]), "+r"(c[1])
        : "r"(a[0]), "r"(a[1]), "r"(a[2]), "r"(a[3]), "r"(b[0]), "r"(b[1]));
}
__device__ __forceinline__ void ldm4(unsigned* r, unsigned addr) {
    asm volatile("ldmatrix.sync.aligned.m8n8.x4.shared.b16 {%0,%1,%2,%3}, [%4];"
        : "=r"(r[0]), "=r"(r[1]), "=r"(r[2]), "=r"(r[3]) : "r"(addr));
}
__device__ __forceinline__ void cpasync16(unsigned dst, const void* src) {
    asm volatile("cp.async.ca.shared.global [%0], [%1], 16;" :: "r"(dst), "l"(src));
}
#define CP_COMMIT() asm volatile("cp.async.commit_group;")
#define CP_WAIT2()  asm volatile("cp.async.wait_group 2;")

// ---------------- P1: layernorm(h0) + attention context + init ----------------
__global__ void k_init(const float* __restrict__ fm, const float* __restrict__ pooled,
                       const float* __restrict__ gamma, const float* __restrict__ beta,
                       const float* __restrict__ attnw, const int* __restrict__ sos) {
    extern __shared__ float dyn[];
    float* sfm = dyn;            // 25088 floats
    float* swf = dyn + 25088;    // 512 floats
    __shared__ float red[256];
    __shared__ float saw[64];
    __shared__ float sstat[2];
    __shared__ float sh0[512];

    int b = blockIdx.x;
    int tid = threadIdx.x;

    const float4* fmb = (const float4*)(fm + (size_t)b * 25088);
    for (int i = tid; i < 6272; i += 256) ((float4*)sfm)[i] = fmb[i];
    for (int i = tid; i < 512; i += 256) swf[i] = attnw[i];

    float x0 = pooled[b * Dn + tid];
    float x1 = pooled[b * Dn + 256 + tid];
    red[tid] = x0 + x1;
    __syncthreads();
    for (int s = 128; s > 0; s >>= 1) {
        if (tid < s) red[tid] += red[tid + s];
        __syncthreads();
    }
    if (tid == 0) sstat[0] = red[0] * (1.0f / Dn);
    __syncthreads();
    float mu = sstat[0];
    float d0 = x0 - mu, d1 = x1 - mu;
    red[tid] = d0 * d0 + d1 * d1;
    __syncthreads();
    for (int s = 128; s > 0; s >>= 1) {
        if (tid < s) red[tid] += red[tid + s];
        __syncthreads();
    }
    if (tid == 0) sstat[1] = rsqrtf(red[0] * (1.0f / Dn) + 1e-5f);
    __syncthreads();
    float rs = sstat[1];
    sh0[tid]       = d0 * rs * gamma[tid]       + beta[tid];
    sh0[256 + tid] = d1 * rs * gamma[256 + tid] + beta[256 + tid];

    if (tid < 49) {
        float sc = 0.f;
        #pragma unroll 8
        for (int d = 0; d < 512; d++) sc += sfm[d * 49 + tid] * swf[d];
        saw[tid] = sc;
    }
    __syncthreads();
    if (tid == 0) {
        float mx = -1e30f;
        for (int p = 0; p < 49; p++) mx = fmaxf(mx, saw[p]);
        float sm = 0.f;
        for (int p = 0; p < 49; p++) { float e = expf(saw[p] - mx); saw[p] = e; sm += e; }
        sstat[0] = 1.0f / sm;
    }
    __syncthreads();
    float inv = sstat[0];

    for (int d = tid; d < 512; d += 256) {
        float acc = 0.f;
        #pragma unroll
        for (int p = 0; p < 49; p++) acc += saw[p] * sfm[d * 49 + p];
        float ctx = acc * inv;
        int idx = b * Dn + d;
        g_ctx[idx] = ctx;
        g_c[idx] = 0.f;
        float hx = ctx + sh0[d];
        __half hi, lo;
        splitf(hx, hi, lo);
        g_Ah[0][idx] = hi;
        g_Al[0][idx] = lo;
    }
    if (tid == 0) {
        g_token[b] = *sos;
        if (b == 0) g_done = 0;
    }
}

// ---------------- one-time: split W_hh into f16 limbs ----------------
__global__ void k_splitW(const float* __restrict__ W) {
    int idx = blockIdx.x * 256 + threadIdx.x;   // 1048576 total
    float x = W[idx];
    __half hi, lo;
    splitf(x, hi, lo);
    g_Bh[idx] = hi;
    g_Bl[idx] = lo;
}
// ---------------- one-time: split proj_w into f16 limbs ----------------
__global__ void k_splitP(const float* __restrict__ P) {
    int idx = blockIdx.x * 256 + threadIdx.x;   // 65536 total
    float x = P[idx];
    __half hi, lo;
    splitf(x, hi, lo);
    g_Ph[idx] = hi;
    g_Pl[idx] = lo;
}
// ---------------- one-time: CP = ctx @ proj_w^T ----------------
__global__ void k_cp(const float* __restrict__ projw) {
    __shared__ float sctx[512];
    int b = blockIdx.x;
    int tid = threadIdx.x;   // 128
    for (int i = tid; i < 512; i += 128) sctx[i] = g_ctx[b * Dn + i];
    __syncthreads();
    const float* P = projw + (size_t)tid * Dn;
    float acc = 0.f;
    #pragma unroll 8
    for (int k = 0; k < 512; k++) acc += sctx[k] * P[k];
    g_CP[b * Vn + tid] = acc;
}

// ---------------- E2 = embed @ W_ih^T + b_ih + b_hh (one-time) ----------------
__global__ __launch_bounds__(256) void k_e2(const float* __restrict__ emb,
                                            const float* __restrict__ Wih,
                                            const float* __restrict__ bih,
                                            const float* __restrict__ bhh) {
    __shared__ __align__(16) float sA[16 * 68];
    __shared__ __align__(16) float sB[16 * 68];
    int m0 = blockIdx.y * 64;
    int n0 = blockIdx.x * 64;
    int tid = threadIdx.x;
    int tx = tid & 15, ty = tid >> 4;
    int lm = tid >> 2;
    int lk = (tid & 3) * 4;
    const float* Ap = emb + (size_t)(m0 + lm) * Dn + lk;
    const float* Bp = Wih + (size_t)(n0 + lm) * Dn + lk;
    float acc[4][4] = {};
    for (int kt = 0; kt < 512; kt += 16) {
        float4 a = *(const float4*)(Ap + kt);
        float4 bb = *(const float4*)(Bp + kt);
        sA[(lk + 0) * 68 + lm] = a.x;  sA[(lk + 1) * 68 + lm] = a.y;
        sA[(lk + 2) * 68 + lm] = a.z;  sA[(lk + 3) * 68 + lm] = a.w;
        sB[(lk + 0) * 68 + lm] = bb.x; sB[(lk + 1) * 68 + lm] = bb.y;
        sB[(lk + 2) * 68 + lm] = bb.z; sB[(lk + 3) * 68 + lm] = bb.w;
        __syncthreads();
        #pragma unroll
        for (int k = 0; k < 16; k++) {
            float4 av = *(const float4*)&sA[k * 68 + ty * 4];
            float4 bv = *(const float4*)&sB[k * 68 + tx * 4];
            float ar[4] = {av.x, av.y, av.z, av.w};
            float br[4] = {bv.x, bv.y, bv.z, bv.w};
            #pragma unroll
            for (int i = 0; i < 4; i++)
                #pragma unroll
                for (int j = 0; j < 4; j++) acc[i][j] += ar[i] * br[j];
        }
        __syncthreads();
    }
    int gj0 = n0 + tx * 4;
    float4 b1 = *(const float4*)&bih[gj0];
    float4 b2 = *(const float4*)&bhh[gj0];
    #pragma unroll
    for (int i = 0; i < 4; i++) {
        int gv = m0 + ty * 4 + i;
        float4 o;
        o.x = acc[i][0] + b1.x + b2.x;
        o.y = acc[i][1] + b1.y + b2.y;
        o.z = acc[i][2] + b1.z + b2.z;
        o.w = acc[i][3] + b1.w + b2.w;
        *(float4*)&g_E2[(size_t)gv * 2048 + gj0] = o;
    }
}

// ---------------- proj_w transpose (one-time, for final standalone logits) -----
__global__ void k_tw(const float* __restrict__ projw) {
    int idx = blockIdx.x * 256 + threadIdx.x;   // 65536 total
    int vv = idx >> 9;
    int kk = idx & 511;
    g_pwT[kk * 128 + vv] = projw[idx];
}

// ---------------- fused per-step kernel: ONE uniform GEMM, N = 2176 ------------
// grid = 136 blocks (8 M-tiles x 17 N-tiles), all on distinct SMs.
// MMA scheme per k16 iter: Ah*Bh in fp32-accum (16 MMA) + scaled cross terms
// Ah*Bl_s, Al_s*Bh in fp16-accum (32 MMA at 2x rate); epilogue adds cross*1/2048.
#define ST_ROW 48
#define OFF_AH 0
#define OFF_AL 6144
#define OFF_BH 12288
#define OFF_BL 18432
#define STAGE_BYTES 24576
#define SMEM_STEP (STAGE_BYTES * 4)   // 96KB

__global__ __launch_bounds__(256, 1) void k_step(int t, const float* __restrict__ projb,
                                                 float* __restrict__ out) {
    extern __shared__ char sdyn[];
    int bid = blockIdx.x;
    int tid = threadIdx.x;
    int lane = tid & 31;
    int wid = tid >> 5;

    int n = bid % 17;            // 0..16
    int m = bid / 17;            // 0..7
    bool isLog = (n == 16);
    int d0 = n * 32;             // gates tiles only
    int bm0 = m * 128;
    int m0w = (wid >> 2) * 64;
    int wn = wid & 3;

    int par = t & 1;
    const __half* Ahp = g_Ah[par];
    const __half* Alp = g_Al[par];

    unsigned sb = (unsigned)__cvta_generic_to_shared(sdyn);

    // ldmatrix lane base addresses (stage 0)
    unsigned aAH[4], aAL[4], bAH[2], bAL[2];
    #pragma unroll
    for (int mi = 0; mi < 4; mi++) {
        int row = m0w + mi * 16 + ((lane >> 3) & 1) * 8 + (lane & 7);
        unsigned off = (unsigned)(row * ST_ROW + ((lane >> 4) & 1) * 16);
        aAH[mi] = sb + OFF_AH + off;
        aAL[mi] = sb + OFF_AL + off;
    }
    #pragma unroll
    for (int pi = 0; pi < 2; pi++) {
        int row = wn * 32 + pi * 16 + ((lane >> 4) & 1) * 8 + (lane & 7);
        unsigned off = (unsigned)(row * ST_ROW + ((lane >> 3) & 1) * 16);
        bAH[pi] = sb + OFF_BH + off;
        bAL[pi] = sb + OFF_BL + off;
    }

    // staging geometry: each thread copies 16B per array per stage
    int srow = tid >> 1, shalf = tid & 1;
    const char* gAh = (const char*)(Ahp + (size_t)(bm0 + srow) * Dn + shalf * 8);
    const char* gAl = (const char*)(Alp + (size_t)(bm0 + srow) * Dn + shalf * 8);
    int grow = isLog ? srow
                     : ((srow >> 3) & 3) * 512 + d0 + (srow >> 5) * 8 + (srow & 7);
    const __half* BhS = isLog ? g_Ph : g_Bh;
    const __half* BlS = isLog ? g_Pl : g_Bl;
    const char* gBh = (const char*)(BhS + (size_t)grow * Dn + shalf * 8);
    const char* gBl = (const char*)(BlS + (size_t)grow * Dn + shalf * 8);
    unsigned stOff = (unsigned)(srow * ST_ROW + shalf * 16);

    float c[4][4][4];
    unsigned ch[4][4][2];          // fp16 cross accumulators (scaled by 2048)
    #pragma unroll
    for (int mi = 0; mi < 4; mi++)
        #pragma unroll
        for (int ni = 0; ni < 4; ni++) {
            #pragma unroll
            for (int q = 0; q < 4; q++) c[mi][ni][q] = 0.f;
            ch[mi][ni][0] = 0u;
            ch[mi][ni][1] = 0u;
        }

    #pragma unroll
    for (int s = 0; s < 3; s++) {
        unsigned so = sb + (unsigned)(s * STAGE_BYTES);
        int go = s * 32;
        cpasync16(so + OFF_AH + stOff, gAh + go);
        cpasync16(so + OFF_AL + stOff, gAl + go);
        cpasync16(so + OFF_BH + stOff, gBh + go);
        cpasync16(so + OFF_BL + stOff, gBl + go);
        CP_COMMIT();
    }

    for (int kt = 0; kt < 32; kt++) {
        CP_WAIT2();
        __syncthreads();
        unsigned so = (unsigned)((kt & 3) * STAGE_BYTES);

        unsigned AH[4][4], AL[4][4], BH[2][4], BL[2][4];
        #pragma unroll
        for (int mi = 0; mi < 4; mi++) { ldm4(AH[mi], aAH[mi] + so); ldm4(AL[mi], aAL[mi] + so); }
        #pragma unroll
        for (int pi = 0; pi < 2; pi++) { ldm4(BH[pi], bAH[pi] + so); ldm4(BL[pi], bAL[pi] + so); }

        if (kt + 3 < 32) {
            unsigned sw = sb + (unsigned)(((kt + 3) & 3) * STAGE_BYTES);
            int go = (kt + 3) * 32;
            cpasync16(sw + OFF_AH + stOff, gAh + go);
            cpasync16(sw + OFF_AL + stOff, gAl + go);
            cpasync16(sw + OFF_BH + stOff, gBh + go);
            cpasync16(sw + OFF_BL + stOff, gBl + go);
        }
        CP_COMMIT();

        // main term: fp32 accumulation
        #pragma unroll
        for (int mi = 0; mi < 4; mi++)
            #pragma unroll
            for (int ni = 0; ni < 4; ni++)
                mma16816(c[mi][ni], AH[mi], &BH[ni >> 1][(ni & 1) * 2]);
        // scaled cross terms: fp16 accumulation (2x rate)
        #pragma unroll
        for (int mi = 0; mi < 4; mi++)
            #pragma unroll
            for (int ni = 0; ni < 4; ni++)
                mma16816h(ch[mi][ni], AH[mi], &BL[ni >> 1][(ni & 1) * 2]);
        #pragma unroll
        for (int mi = 0; mi < 4; mi++)
            #pragma unroll
            for (int ni = 0; ni < 4; ni++)
                mma16816h(ch[mi][ni], AL[mi], &BH[ni >> 1][(ni & 1) * 2]);
    }

    int g = lane >> 2, tg = lane & 3;

    if (isLog) {
        // ============ LOGITS(t-1) epilogue ============
        if (t == 0) return;
        int ts = t - 1;
        __syncthreads();                       // all warps done reading staging smem
        float* sL = (float*)sdyn;              // 128 x 132

        #pragma unroll
        for (int mi = 0; mi < 4; mi++) {
            #pragma unroll
            for (int ni = 0; ni < 4; ni++) {
                int v0 = wn * 32 + ni * 8 + tg * 2;
                float2 pb = *(const float2*)&projb[v0];
                #pragma unroll
                for (int q = 0; q < 2; q++) {
                    int lrow = m0w + mi * 16 + g + q * 8;
                    int row = bm0 + lrow;
                    float2 cp = *(const float2*)&g_CP[row * Vn + v0];
                    float2 cr = __half22float2(*(__half2*)&ch[mi][ni][q]);
                    float lg0 = c[mi][ni][q * 2 + 0] + cr.x * LINV - cp.x + pb.x;
                    float lg1 = c[mi][ni][q * 2 + 1] + cr.y * LINV - cp.y + pb.y;
                    *(float2*)&sL[lrow * 132 + v0] = make_float2(lg0, lg1);
                    out[(size_t)row * (Vn * Tn) + (size_t)v0 * Tn + ts] = lg0;
                    out[(size_t)row * (Vn * Tn) + (size_t)(v0 + 1) * Tn + ts] = lg1;
                }
            }
        }
        __syncthreads();

        // argmax: warp wid handles rows wid*16 .. +15 (first-max tiebreak)
        for (int r = 0; r < 16; r++) {
            int lrow = wid * 16 + r;
            float best = sL[lrow * 132 + lane];
            int bi = lane;
            #pragma unroll
            for (int off = 32; off < 128; off += 32) {
                float vv = sL[lrow * 132 + lane + off];
                if (vv > best) { best = vv; bi = lane + off; }
            }
            #pragma unroll
            for (int s = 16; s > 0; s >>= 1) {
                float ov = __shfl_down_sync(0xffffffffu, best, s);
                int oi = __shfl_down_sync(0xffffffffu, bi, s);
                if (ov > best || (ov == best && oi < bi)) { best = ov; bi = oi; }
            }
            if (lane == 0) g_token[bm0 + lrow] = bi;
        }
        __syncthreads();
        __threadfence();
        if (tid == 0) atomicAdd(&g_done, 1);
    } else {
        // ============ GATES(t) epilogue ============
        __half* AhO = g_Ah[par ^ 1];
        __half* AlO = g_Al[par ^ 1];

        // wait for this launch's 8 logits blocks (token(t-1) producers)
        if (tid == 0) {
            int target = 8 * t;
            while (atomicAdd(&g_done, 0) < target) {}
            __threadfence();
        }
        __syncthreads();

        int ddb = wn * 8 + tg * 2;
        #pragma unroll
        for (int mi = 0; mi < 4; mi++) {
            #pragma unroll
            for (int q = 0; q < 2; q++) {
                int row = bm0 + m0w + mi * 16 + g + q * 8;
                int tok = g_token[row];
                const float* E = g_E2 + (size_t)tok * 2048 + d0 + ddb;
                float2 ei = *(const float2*)(E);
                float2 ef = *(const float2*)(E + 512);
                float2 eg = *(const float2*)(E + 1024);
                float2 eo = *(const float2*)(E + 1536);
                int idx = row * Dn + d0 + ddb;
                float2 cold = *(const float2*)&g_c[idx];
                float2 ctx = *(const float2*)&g_ctx[idx];

                float2 cri = __half22float2(*(__half2*)&ch[mi][0][q]);
                float2 crf = __half22float2(*(__half2*)&ch[mi][1][q]);
                float2 crg = __half22float2(*(__half2*)&ch[mi][2][q]);
                float2 cro = __half22float2(*(__half2*)&ch[mi][3][q]);

                float gi = c[mi][0][q * 2 + 0] + cri.x * LINV + ei.x;
                float gf = c[mi][1][q * 2 + 0] + crf.x * LINV + ef.x;
                float gg = c[mi][2][q * 2 + 0] + crg.x * LINV + eg.x;
                float go = c[mi][3][q * 2 + 0] + cro.x * LINV + eo.x;
                float cn0 = sigexact(gf) * cold.x + sigexact(gi) * tanhf(gg);
                float hn0 = sigexact(go) * tanhf(cn0);

                gi = c[mi][0][q * 2 + 1] + cri.y * LINV + ei.y;
                gf = c[mi][1][q * 2 + 1] + crf.y * LINV + ef.y;
                gg = c[mi][2][q * 2 + 1] + crg.y * LINV + eg.y;
                go = c[mi][3][q * 2 + 1] + cro.y * LINV + eo.y;
                float cn1 = sigexact(gf) * cold.y + sigexact(gi) * tanhf(gg);
                float hn1 = sigexact(go) * tanhf(cn1);

                *(float2*)&g_c[idx] = make_float2(cn0, cn1);
                *(float2*)&g_h[idx] = make_float2(hn0, hn1);
                float hx0 = hn0 + ctx.x;
                float hx1 = hn1 + ctx.y;
                __half h0h, h0l, h1h, h1l;
                splitf(hx0, h0h, h0l);
                splitf(hx1, h1h, h1l);
                *(__half2*)&AhO[idx] = __halves2half2(h0h, h1h);
                *(__half2*)&AlO[idx] = __halves2half2(h0l, h1l);
            }
        }
    }
}

// ---------------- standalone final logits (step Tn-1) ----------------
__global__ __launch_bounds__(256) void k_logits(int t, const float* __restrict__ projb,
                                                float* __restrict__ out) {
    __shared__ __align__(16) float sHT[512 * 12];

    int b0 = blockIdx.x * 8;
    int tid = threadIdx.x;
    int lane = tid & 31;
    int wid = tid >> 5;

    {
        int row = wid;
        #pragma unroll
        for (int it = 0; it < 4; it++) {
            int k4 = lane + 32 * it;
            float4 hv = *(const float4*)&g_h[(size_t)(b0 + row) * Dn + k4 * 4];
            sHT[(k4 * 4 + 0) * 12 + row] = hv.x;
            sHT[(k4 * 4 + 1) * 12 + row] = hv.y;
            sHT[(k4 * 4 + 2) * 12 + row] = hv.z;
            sHT[(k4 * 4 + 3) * 12 + row] = hv.w;
        }
    }
    __syncthreads();

    int rbase = (wid >> 2) * 4;
    int v = (wid & 3) * 32 + lane;
    const float* P = g_pwT + v;

    float a0 = 0.f, a1 = 0.f, a2 = 0.f, a3 = 0.f;
    #pragma unroll 4
    for (int k = 0; k < 512; k += 4) {
        float p0 = __ldg(&P[(k + 0) * 128]);
        float p1 = __ldg(&P[(k + 1) * 128]);
        float p2 = __ldg(&P[(k + 2) * 128]);
        float p3 = __ldg(&P[(k + 3) * 128]);
        float4 hA = *(const float4*)&sHT[(k + 0) * 12 + rbase];
        float4 hB = *(const float4*)&sHT[(k + 1) * 12 + rbase];
        float4 hC = *(const float4*)&sHT[(k + 2) * 12 + rbase];
        float4 hD = *(const float4*)&sHT[(k + 3) * 12 + rbase];
        a0 += hA.x * p0 + hB.x * p1 + hC.x * p2 + hD.x * p3;
        a1 += hA.y * p0 + hB.y * p1 + hC.y * p2 + hD.y * p3;
        a2 += hA.z * p0 + hB.z * p1 + hC.z * p2 + hD.z * p3;
        a3 += hA.w * p0 + hB.w * p1 + hC.w * p2 + hD.w * p3;
    }

    float pb = projb[v];
    #pragma unroll
    for (int r = 0; r < 4; r++)
        out[(size_t)(b0 + rbase + r) * (Vn * Tn) + (size_t)v * Tn + t] =
            ((r == 0) ? a0 : (r == 1) ? a1 : (r == 2) ? a2 : a3) + pb;
}

// ---------------- launch ----------------
extern "C" void kernel_launch(void* const* d_in, const int* in_sizes, int n_in,
                              void* d_out, int out_size) {
    const float* fm     = (const float*)d_in[0];
    const float* pooled = (const float*)d_in[1];
    const float* gamma  = (const float*)d_in[2];
    const float* beta   = (const float*)d_in[3];
    const float* Wih    = (const float*)d_in[4];
    const float* Whh    = (const float*)d_in[5];
    const float* bih    = (const float*)d_in[6];
    const float* bhh    = (const float*)d_in[7];
    const float* emb    = (const float*)d_in[8];
    const float* attnw  = (const float*)d_in[9];
    // d_in[10] = attn_b: cancels in softmax (constant over the axis)
    const float* projw  = (const float*)d_in[11];
    const float* projb  = (const float*)d_in[12];
    const int*   sos    = (const int*)d_in[13];
    float* out = (float*)d_out;

    const int dynBytes = (25088 + 512) * 4;
    cudaFuncSetAttribute(k_init, cudaFuncAttributeMaxDynamicSharedMemorySize, dynBytes);
    cudaFuncSetAttribute(k_step, cudaFuncAttributeMaxDynamicSharedMemorySize, SMEM_STEP);

    k_init<<<Bn, 256, dynBytes>>>(fm, pooled, gamma, beta, attnw, sos);
    k_splitW<<<4096, 256>>>(Whh);
    k_splitP<<<256, 256>>>(projw);
    k_e2<<<dim3(32, 2), 256>>>(emb, Wih, bih, bhh);
    k_tw<<<256, 256>>>(projw);
    k_cp<<<Bn, 128>>>(projw);

    for (int t = 0; t < Tn; t++) {
        k_step<<<136, 256, SMEM_STEP>>>(t, projb, out);
    }
    k_logits<<<128, 256>>>(Tn - 1, projb, out);
}

// round 12
// speedup vs baseline: 1.2192x; 1.2192x over previous
#include <cuda_runtime.h>
#include <cuda_fp16.h>
#include <math.h>

#define Bn 1024
#define Dn 512
#define Vn 128
#define Tn 201
#define NBLK 136

// ---------------- device scratch ----------------
__device__ float  g_h[Bn * Dn];            // h_t (read by final standalone logits)
__device__ float  g_c[Bn * Dn];
__device__ float  g_ctx[Bn * Dn];
__device__ __half g_Ah[2][Bn * Dn];        // ping-pong hx hi-limb
__device__ __half g_Al[2][Bn * Dn];        // ping-pong hx lo-limb
__device__ __half g_Bh[4 * Dn * Dn];       // W_hh hi-limb [2048x512]
__device__ __half g_Bl[4 * Dn * Dn];       // W_hh lo-limb
__device__ __half g_Ph[Vn * Dn];           // proj_w hi-limb [128x512]
__device__ __half g_Pl[Vn * Dn];           // proj_w lo-limb
__device__ float  g_E2[Vn * 4 * Dn];       // embed @ W_ih^T + b_ih + b_hh
__device__ float  g_pwT[Dn * Vn];          // proj_w transposed [K][V] (final logits)
__device__ float  g_CP[Bn * Vn];           // ctx @ proj_w^T  (time-invariant)
__device__ int    g_token[Bn];
__device__ int    g_done;                  // cumulative finished logits blocks
__device__ unsigned g_barcnt;              // grid barrier arrive count
__device__ unsigned g_bargen;              // grid barrier generation

__device__ __forceinline__ float sigexact(float x) {
    return 1.f / (1.f + expf(-x));
}
__device__ __forceinline__ void splitf(float x, __half& hi, __half& lo) {
    hi = __float2half_rn(x);
    lo = __float2half_rn(x - __half2float(hi));
}

// ---------------- mma / ldmatrix / cp.async wrappers ----------------
__device__ __forceinline__ void mma16816(float* c, const unsigned* a, const unsigned* b) {
    asm volatile(
        "mma.sync.aligned.m16n8k16.row.col.f32.f16.f16.f32 "
        "{%0,%1,%2,%3}, {%4,%5,%6,%7}, {%8,%9}, {%0,%1,%2,%3};"
        : "+f"(c[0]), "+f"(c[1]), "+f"(c[2]), "+f"(c[3])
        : "r"(a[0]), "r"(a[1]), "r"(a[2]), "r"(a[3]), "r"(b[0]), "r"(b[1]));
}
__device__ __forceinline__ void ldm4(unsigned* r, unsigned addr) {
    asm volatile("ldmatrix.sync.aligned.m8n8.x4.shared.b16 {%0,%1,%2,%3}, [%4];"
        : "=r"(r[0]), "=r"(r[1]), "=r"(r[2]), "=r"(r[3]) : "r"(addr));
}
__device__ __forceinline__ void cpasync16(unsigned dst, const void* src) {
    asm volatile("cp.async.ca.shared.global [%0], [%1], 16;" :: "r"(dst), "l"(src));
}
#define CP_COMMIT() asm volatile("cp.async.commit_group;")
#define CP_WAIT2()  asm volatile("cp.async.wait_group 2;")

// ---------------- P1: layernorm(h0) + attention context + init ----------------
__global__ void k_init(const float* __restrict__ fm, const float* __restrict__ pooled,
                       const float* __restrict__ gamma, const float* __restrict__ beta,
                       const float* __restrict__ attnw, const int* __restrict__ sos) {
    extern __shared__ float dyn[];
    float* sfm = dyn;            // 25088 floats
    float* swf = dyn + 25088;    // 512 floats
    __shared__ float red[256];
    __shared__ float saw[64];
    __shared__ float sstat[2];
    __shared__ float sh0[512];

    int b = blockIdx.x;
    int tid = threadIdx.x;

    const float4* fmb = (const float4*)(fm + (size_t)b * 25088);
    for (int i = tid; i < 6272; i += 256) ((float4*)sfm)[i] = fmb[i];
    for (int i = tid; i < 512; i += 256) swf[i] = attnw[i];

    float x0 = pooled[b * Dn + tid];
    float x1 = pooled[b * Dn + 256 + tid];
    red[tid] = x0 + x1;
    __syncthreads();
    for (int s = 128; s > 0; s >>= 1) {
        if (tid < s) red[tid] += red[tid + s];
        __syncthreads();
    }
    if (tid == 0) sstat[0] = red[0] * (1.0f / Dn);
    __syncthreads();
    float mu = sstat[0];
    float d0 = x0 - mu, d1 = x1 - mu;
    red[tid] = d0 * d0 + d1 * d1;
    __syncthreads();
    for (int s = 128; s > 0; s >>= 1) {
        if (tid < s) red[tid] += red[tid + s];
        __syncthreads();
    }
    if (tid == 0) sstat[1] = rsqrtf(red[0] * (1.0f / Dn) + 1e-5f);
    __syncthreads();
    float rs = sstat[1];
    sh0[tid]       = d0 * rs * gamma[tid]       + beta[tid];
    sh0[256 + tid] = d1 * rs * gamma[256 + tid] + beta[256 + tid];

    if (tid < 49) {
        float sc = 0.f;
        #pragma unroll 8
        for (int d = 0; d < 512; d++) sc += sfm[d * 49 + tid] * swf[d];
        saw[tid] = sc;
    }
    __syncthreads();
    if (tid == 0) {
        float mx = -1e30f;
        for (int p = 0; p < 49; p++) mx = fmaxf(mx, saw[p]);
        float sm = 0.f;
        for (int p = 0; p < 49; p++) { float e = expf(saw[p] - mx); saw[p] = e; sm += e; }
        sstat[0] = 1.0f / sm;
    }
    __syncthreads();
    float inv = sstat[0];

    for (int d = tid; d < 512; d += 256) {
        float acc = 0.f;
        #pragma unroll
        for (int p = 0; p < 49; p++) acc += saw[p] * sfm[d * 49 + p];
        float ctx = acc * inv;
        int idx = b * Dn + d;
        g_ctx[idx] = ctx;
        g_c[idx] = 0.f;
        float hx = ctx + sh0[d];
        __half hi, lo;
        splitf(hx, hi, lo);
        g_Ah[0][idx] = hi;
        g_Al[0][idx] = lo;
    }
    if (tid == 0) {
        g_token[b] = *sos;
        if (b == 0) { g_done = 0; g_barcnt = 0; g_bargen = 0; }
    }
}

// ---------------- one-time: split W_hh / proj_w into f16 limbs ----------------
__global__ void k_splitW(const float* __restrict__ W) {
    int idx = blockIdx.x * 256 + threadIdx.x;   // 1048576 total
    float x = W[idx];
    __half hi, lo;
    splitf(x, hi, lo);
    g_Bh[idx] = hi;
    g_Bl[idx] = lo;
}
__global__ void k_splitP(const float* __restrict__ P) {
    int idx = blockIdx.x * 256 + threadIdx.x;   // 65536 total
    float x = P[idx];
    __half hi, lo;
    splitf(x, hi, lo);
    g_Ph[idx] = hi;
    g_Pl[idx] = lo;
}
// ---------------- one-time: CP = ctx @ proj_w^T ----------------
__global__ void k_cp(const float* __restrict__ projw) {
    __shared__ float sctx[512];
    int b = blockIdx.x;
    int tid = threadIdx.x;   // 128
    for (int i = tid; i < 512; i += 128) sctx[i] = g_ctx[b * Dn + i];
    __syncthreads();
    const float* P = projw + (size_t)tid * Dn;
    float acc = 0.f;
    #pragma unroll 8
    for (int k = 0; k < 512; k++) acc += sctx[k] * P[k];
    g_CP[b * Vn + tid] = acc;
}

// ---------------- E2 = embed @ W_ih^T + b_ih + b_hh (one-time) ----------------
__global__ __launch_bounds__(256) void k_e2(const float* __restrict__ emb,
                                            const float* __restrict__ Wih,
                                            const float* __restrict__ bih,
                                            const float* __restrict__ bhh) {
    __shared__ __align__(16) float sA[16 * 68];
    __shared__ __align__(16) float sB[16 * 68];
    int m0 = blockIdx.y * 64;
    int n0 = blockIdx.x * 64;
    int tid = threadIdx.x;
    int tx = tid & 15, ty = tid >> 4;
    int lm = tid >> 2;
    int lk = (tid & 3) * 4;
    const float* Ap = emb + (size_t)(m0 + lm) * Dn + lk;
    const float* Bp = Wih + (size_t)(n0 + lm) * Dn + lk;
    float acc[4][4] = {};
    for (int kt = 0; kt < 512; kt += 16) {
        float4 a = *(const float4*)(Ap + kt);
        float4 bb = *(const float4*)(Bp + kt);
        sA[(lk + 0) * 68 + lm] = a.x;  sA[(lk + 1) * 68 + lm] = a.y;
        sA[(lk + 2) * 68 + lm] = a.z;  sA[(lk + 3) * 68 + lm] = a.w;
        sB[(lk + 0) * 68 + lm] = bb.x; sB[(lk + 1) * 68 + lm] = bb.y;
        sB[(lk + 2) * 68 + lm] = bb.z; sB[(lk + 3) * 68 + lm] = bb.w;
        __syncthreads();
        #pragma unroll
        for (int k = 0; k < 16; k++) {
            float4 av = *(const float4*)&sA[k * 68 + ty * 4];
            float4 bv = *(const float4*)&sB[k * 68 + tx * 4];
            float ar[4] = {av.x, av.y, av.z, av.w};
            float br[4] = {bv.x, bv.y, bv.z, bv.w};
            #pragma unroll
            for (int i = 0; i < 4; i++)
                #pragma unroll
                for (int j = 0; j < 4; j++) acc[i][j] += ar[i] * br[j];
        }
        __syncthreads();
    }
    int gj0 = n0 + tx * 4;
    float4 b1 = *(const float4*)&bih[gj0];
    float4 b2 = *(const float4*)&bhh[gj0];
    #pragma unroll
    for (int i = 0; i < 4; i++) {
        int gv = m0 + ty * 4 + i;
        float4 o;
        o.x = acc[i][0] + b1.x + b2.x;
        o.y = acc[i][1] + b1.y + b2.y;
        o.z = acc[i][2] + b1.z + b2.z;
        o.w = acc[i][3] + b1.w + b2.w;
        *(float4*)&g_E2[(size_t)gv * 2048 + gj0] = o;
    }
}

// ---------------- proj_w transpose (one-time, for final standalone logits) -----
__global__ void k_tw(const float* __restrict__ projw) {
    int idx = blockIdx.x * 256 + threadIdx.x;   // 65536 total
    int vv = idx >> 9;
    int kk = idx & 511;
    g_pwT[kk * 128 + vv] = projw[idx];
}

// ---------------- PERSISTENT kernel: all 201 steps, grid-wide barrier ----------
// grid = 136 blocks (8 M x 17 N), all co-resident (1/SM). N-tile 16 = logits.
// Per iteration: [A issue x3] -> mainloop (32 k16, wait_group 2 invariant)
//   -> B prefetch for next iter (weights are step-invariant; 1 group)
//   -> role epilogue (logits: argmax FIRST, release, then out stores)
//   -> grid barrier (sense-reversal on g_barcnt/g_bargen).
#define ST_ROW 48
#define OFF_AH 0
#define OFF_AL 6144
#define OFF_BH 12288
#define OFF_BL 18432
#define STAGE_BYTES 24576
#define SMEM_STEP (STAGE_BYTES * 4)   // 96KB

__global__ __launch_bounds__(256, 1) void k_steps(const float* __restrict__ projb,
                                                  float* __restrict__ out) {
    extern __shared__ char sdyn[];
    int bid = blockIdx.x;
    int tid = threadIdx.x;
    int lane = tid & 31;
    int wid = tid >> 5;

    int n = bid % 17;            // 0..16
    int m = bid / 17;            // 0..7
    bool isLog = (n == 16);
    int d0 = n * 32;             // gates tiles only
    int bm0 = m * 128;
    int m0w = (wid >> 2) * 64;
    int wn = wid & 3;

    unsigned sb = (unsigned)__cvta_generic_to_shared(sdyn);

    // ldmatrix lane base addresses (stage 0)
    unsigned aAH[4], aAL[4], bAH[2], bAL[2];
    #pragma unroll
    for (int mi = 0; mi < 4; mi++) {
        int row = m0w + mi * 16 + ((lane >> 3) & 1) * 8 + (lane & 7);
        unsigned off = (unsigned)(row * ST_ROW + ((lane >> 4) & 1) * 16);
        aAH[mi] = sb + OFF_AH + off;
        aAL[mi] = sb + OFF_AL + off;
    }
    #pragma unroll
    for (int pi = 0; pi < 2; pi++) {
        int row = wn * 32 + pi * 16 + ((lane >> 4) & 1) * 8 + (lane & 7);
        unsigned off = (unsigned)(row * ST_ROW + ((lane >> 3) & 1) * 16);
        bAH[pi] = sb + OFF_BH + off;
        bAL[pi] = sb + OFF_BL + off;
    }

    // staging geometry: each thread copies 16B per array per stage
    int srow = tid >> 1, shalf = tid & 1;
    size_t aoff = (size_t)(bm0 + srow) * Dn + shalf * 8;
    int grow = isLog ? srow
                     : ((srow >> 3) & 3) * 512 + d0 + (srow >> 5) * 8 + (srow & 7);
    const __half* BhS = isLog ? g_Ph : g_Bh;
    const __half* BlS = isLog ? g_Pl : g_Bl;
    const char* gBh = (const char*)(BhS + (size_t)grow * Dn + shalf * 8);
    const char* gBl = (const char*)(BlS + (size_t)grow * Dn + shalf * 8);
    unsigned stOff = (unsigned)(srow * ST_ROW + shalf * 16);

    // prologue: B for stages 0..2 (weights; one commit group)
    #pragma unroll
    for (int s = 0; s < 3; s++) {
        unsigned so = sb + (unsigned)(s * STAGE_BYTES);
        int go = s * 32;
        cpasync16(so + OFF_BH + stOff, gBh + go);
        cpasync16(so + OFF_BL + stOff, gBl + go);
    }
    CP_COMMIT();

    for (int t = 0; t < Tn; t++) {
        int par = t & 1;
        const char* gAh = (const char*)(g_Ah[par]) + aoff * 2;   // *2 bytes per half
        const char* gAl = (const char*)(g_Al[par]) + aoff * 2;

        // A stage issues: 3 commit groups
        #pragma unroll
        for (int s = 0; s < 3; s++) {
            unsigned so = sb + (unsigned)(s * STAGE_BYTES);
            int go = s * 32;
            cpasync16(so + OFF_AH + stOff, gAh + go);
            cpasync16(so + OFF_AL + stOff, gAl + go);
            CP_COMMIT();
        }

        float c[4][4][4];
        #pragma unroll
        for (int mi = 0; mi < 4; mi++)
            #pragma unroll
            for (int ni = 0; ni < 4; ni++)
                #pragma unroll
                for (int q = 0; q < 4; q++) c[mi][ni][q] = 0.f;

        for (int kt = 0; kt < 32; kt++) {
            CP_WAIT2();
            __syncthreads();
            unsigned so = (unsigned)((kt & 3) * STAGE_BYTES);

            unsigned AH[4][4], AL[4][4], BH[2][4], BL[2][4];
            #pragma unroll
            for (int mi = 0; mi < 4; mi++) { ldm4(AH[mi], aAH[mi] + so); ldm4(AL[mi], aAL[mi] + so); }
            #pragma unroll
            for (int pi = 0; pi < 2; pi++) { ldm4(BH[pi], bAH[pi] + so); ldm4(BL[pi], bAL[pi] + so); }

            if (kt + 3 < 32) {
                unsigned sw = sb + (unsigned)(((kt + 3) & 3) * STAGE_BYTES);
                int go = (kt + 3) * 32;
                cpasync16(sw + OFF_AH + stOff, gAh + go);
                cpasync16(sw + OFF_AL + stOff, gAl + go);
                cpasync16(sw + OFF_BH + stOff, gBh + go);
                cpasync16(sw + OFF_BL + stOff, gBl + go);
            }
            CP_COMMIT();

            #pragma unroll
            for (int mi = 0; mi < 4; mi++)
                #pragma unroll
                for (int ni = 0; ni < 4; ni++)
                    mma16816(c[mi][ni], AH[mi], &BH[ni >> 1][(ni & 1) * 2]);
            #pragma unroll
            for (int mi = 0; mi < 4; mi++)
                #pragma unroll
                for (int ni = 0; ni < 4; ni++)
                    mma16816(c[mi][ni], AH[mi], &BL[ni >> 1][(ni & 1) * 2]);
            #pragma unroll
            for (int mi = 0; mi < 4; mi++)
                #pragma unroll
                for (int ni = 0; ni < 4; ni++)
                    mma16816(c[mi][ni], AL[mi], &BH[ni >> 1][(ni & 1) * 2]);
        }

        int g = lane >> 2, tg = lane & 3;

        if (isLog) {
            // ============ LOGITS(t-1) epilogue ============
            if (t > 0) {
                int ts = t - 1;
                __syncthreads();                   // staging reads done; reuse sdyn
                float* sL = (float*)sdyn;          // 128 x 132

                #pragma unroll
                for (int mi = 0; mi < 4; mi++) {
                    #pragma unroll
                    for (int ni = 0; ni < 4; ni++) {
                        int v0 = wn * 32 + ni * 8 + tg * 2;
                        float2 pb = *(const float2*)&projb[v0];
                        #pragma unroll
                        for (int q = 0; q < 2; q++) {
                            int lrow = m0w + mi * 16 + g + q * 8;
                            int row = bm0 + lrow;
                            float2 cp = *(const float2*)&g_CP[row * Vn + v0];
                            float lg0 = c[mi][ni][q * 2 + 0] - cp.x + pb.x;
                            float lg1 = c[mi][ni][q * 2 + 1] - cp.y + pb.y;
                            *(float2*)&sL[lrow * 132 + v0] = make_float2(lg0, lg1);
                        }
                    }
                }
                __syncthreads();

                // argmax FIRST (token critical path), then release
                for (int r = 0; r < 16; r++) {
                    int lrow = wid * 16 + r;
                    float best = sL[lrow * 132 + lane];
                    int bi = lane;
                    #pragma unroll
                    for (int off = 32; off < 128; off += 32) {
                        float vv = sL[lrow * 132 + lane + off];
                        if (vv > best) { best = vv; bi = lane + off; }
                    }
                    #pragma unroll
                    for (int s = 16; s > 0; s >>= 1) {
                        float ov = __shfl_down_sync(0xffffffffu, best, s);
                        int oi = __shfl_down_sync(0xffffffffu, bi, s);
                        if (ov > best || (ov == best && oi < bi)) { best = ov; bi = oi; }
                    }
                    if (lane == 0) g_token[bm0 + lrow] = bi;
                }
                __syncthreads();
                __threadfence();
                if (tid == 0) atomicAdd(&g_done, 1);

                // deferred output stores (off critical path)
                for (int i = tid; i < 128 * 128; i += 256) {
                    int lr = i >> 7, v = i & 127;
                    out[(size_t)(bm0 + lr) * (Vn * Tn) + (size_t)v * Tn + ts] =
                        sL[lr * 132 + v];
                }
                __syncthreads();                   // all sL reads done before B prefetch
            }
            // next-iter B prefetch (after sL is dead)
            if (t + 1 < Tn) {
                #pragma unroll
                for (int s = 0; s < 3; s++) {
                    unsigned so = sb + (unsigned)(s * STAGE_BYTES);
                    int go = s * 32;
                    cpasync16(so + OFF_BH + stOff, gBh + go);
                    cpasync16(so + OFF_BL + stOff, gBl + go);
                }
            }
            CP_COMMIT();
        } else {
            // next-iter B prefetch immediately (overlaps token wait)
            if (t + 1 < Tn) {
                #pragma unroll
                for (int s = 0; s < 3; s++) {
                    unsigned so = sb + (unsigned)(s * STAGE_BYTES);
                    int go = s * 32;
                    cpasync16(so + OFF_BH + stOff, gBh + go);
                    cpasync16(so + OFF_BL + stOff, gBl + go);
                }
            }
            CP_COMMIT();

            // ============ GATES(t) epilogue ============
            __half* AhO = g_Ah[par ^ 1];
            __half* AlO = g_Al[par ^ 1];

            if (tid == 0) {
                int target = 8 * t;
                while (*(volatile int*)&g_done < target) {}
                __threadfence();
            }
            __syncthreads();

            int ddb = wn * 8 + tg * 2;
            #pragma unroll
            for (int mi = 0; mi < 4; mi++) {
                #pragma unroll
                for (int q = 0; q < 2; q++) {
                    int row = bm0 + m0w + mi * 16 + g + q * 8;
                    int tok = g_token[row];
                    const float* E = g_E2 + (size_t)tok * 2048 + d0 + ddb;
                    float2 ei = *(const float2*)(E);
                    float2 ef = *(const float2*)(E + 512);
                    float2 eg = *(const float2*)(E + 1024);
                    float2 eo = *(const float2*)(E + 1536);
                    int idx = row * Dn + d0 + ddb;
                    float2 cold = *(const float2*)&g_c[idx];
                    float2 ctx = *(const float2*)&g_ctx[idx];

                    float gi = c[mi][0][q * 2 + 0] + ei.x;
                    float gf = c[mi][1][q * 2 + 0] + ef.x;
                    float gg = c[mi][2][q * 2 + 0] + eg.x;
                    float go = c[mi][3][q * 2 + 0] + eo.x;
                    float cn0 = sigexact(gf) * cold.x + sigexact(gi) * tanhf(gg);
                    float hn0 = sigexact(go) * tanhf(cn0);

                    gi = c[mi][0][q * 2 + 1] + ei.y;
                    gf = c[mi][1][q * 2 + 1] + ef.y;
                    gg = c[mi][2][q * 2 + 1] + eg.y;
                    go = c[mi][3][q * 2 + 1] + eo.y;
                    float cn1 = sigexact(gf) * cold.y + sigexact(gi) * tanhf(gg);
                    float hn1 = sigexact(go) * tanhf(cn1);

                    *(float2*)&g_c[idx] = make_float2(cn0, cn1);
                    *(float2*)&g_h[idx] = make_float2(hn0, hn1);
                    float hx0 = hn0 + ctx.x;
                    float hx1 = hn1 + ctx.y;
                    __half h0h, h0l, h1h, h1l;
                    splitf(hx0, h0h, h0l);
                    splitf(hx1, h1h, h1l);
                    *(__half2*)&AhO[idx] = __halves2half2(h0h, h1h);
                    *(__half2*)&AlO[idx] = __halves2half2(h0l, h1l);
                }
            }
        }

        // ================= grid barrier =================
        __threadfence();
        __syncthreads();
        if (tid == 0) {
            unsigned old = atomicAdd(&g_barcnt, 1);
            if (old == (unsigned)(NBLK - 1)) {
                g_barcnt = 0;
                __threadfence();
                *(volatile unsigned*)&g_bargen = (unsigned)(t + 1);
            } else {
                while (*(volatile unsigned*)&g_bargen < (unsigned)(t + 1)) {}
                __threadfence();
            }
        }
        __syncthreads();
    }
}

// ---------------- standalone final logits (step Tn-1) ----------------
__global__ __launch_bounds__(256) void k_logits(int t, const float* __restrict__ projb,
                                                float* __restrict__ out) {
    __shared__ __align__(16) float sHT[512 * 12];

    int b0 = blockIdx.x * 8;
    int tid = threadIdx.x;
    int lane = tid & 31;
    int wid = tid >> 5;

    {
        int row = wid;
        #pragma unroll
        for (int it = 0; it < 4; it++) {
            int k4 = lane + 32 * it;
            float4 hv = *(const float4*)&g_h[(size_t)(b0 + row) * Dn + k4 * 4];
            sHT[(k4 * 4 + 0) * 12 + row] = hv.x;
            sHT[(k4 * 4 + 1) * 12 + row] = hv.y;
            sHT[(k4 * 4 + 2) * 12 + row] = hv.z;
            sHT[(k4 * 4 + 3) * 12 + row] = hv.w;
        }
    }
    __syncthreads();

    int rbase = (wid >> 2) * 4;
    int v = (wid & 3) * 32 + lane;
    const float* P = g_pwT + v;

    float a0 = 0.f, a1 = 0.f, a2 = 0.f, a3 = 0.f;
    #pragma unroll 4
    for (int k = 0; k < 512; k += 4) {
        float p0 = __ldg(&P[(k + 0) * 128]);
        float p1 = __ldg(&P[(k + 1) * 128]);
        float p2 = __ldg(&P[(k + 2) * 128]);
        float p3 = __ldg(&P[(k + 3) * 128]);
        float4 hA = *(const float4*)&sHT[(k + 0) * 12 + rbase];
        float4 hB = *(const float4*)&sHT[(k + 1) * 12 + rbase];
        float4 hC = *(const float4*)&sHT[(k + 2) * 12 + rbase];
        float4 hD = *(const float4*)&sHT[(k + 3) * 12 + rbase];
        a0 += hA.x * p0 + hB.x * p1 + hC.x * p2 + hD.x * p3;
        a1 += hA.y * p0 + hB.y * p1 + hC.y * p2 + hD.y * p3;
        a2 += hA.z * p0 + hB.z * p1 + hC.z * p2 + hD.z * p3;
        a3 += hA.w * p0 + hB.w * p1 + hC.w * p2 + hD.w * p3;
    }

    float pb = projb[v];
    #pragma unroll
    for (int r = 0; r < 4; r++)
        out[(size_t)(b0 + rbase + r) * (Vn * Tn) + (size_t)v * Tn + t] =
            ((r == 0) ? a0 : (r == 1) ? a1 : (r == 2) ? a2 : a3) + pb;
}

// ---------------- launch ----------------
extern "C" void kernel_launch(void* const* d_in, const int* in_sizes, int n_in,
                              void* d_out, int out_size) {
    const float* fm     = (const float*)d_in[0];
    const float* pooled = (const float*)d_in[1];
    const float* gamma  = (const float*)d_in[2];
    const float* beta   = (const float*)d_in[3];
    const float* Wih    = (const float*)d_in[4];
    const float* Whh    = (const float*)d_in[5];
    const float* bih    = (const float*)d_in[6];
    const float* bhh    = (const float*)d_in[7];
    const float* emb    = (const float*)d_in[8];
    const float* attnw  = (const float*)d_in[9];
    // d_in[10] = attn_b: cancels in softmax (constant over the axis)
    const float* projw  = (const float*)d_in[11];
    const float* projb  = (const float*)d_in[12];
    const int*   sos    = (const int*)d_in[13];
    float* out = (float*)d_out;

    const int dynBytes = (25088 + 512) * 4;
    cudaFuncSetAttribute(k_init, cudaFuncAttributeMaxDynamicSharedMemorySize, dynBytes);
    cudaFuncSetAttribute(k_steps, cudaFuncAttributeMaxDynamicSharedMemorySize, SMEM_STEP);

    k_init<<<Bn, 256, dynBytes>>>(fm, pooled, gamma, beta, attnw, sos);
    k_splitW<<<4096, 256>>>(Whh);
    k_splitP<<<256, 256>>>(projw);
    k_e2<<<dim3(32, 2), 256>>>(emb, Wih, bih, bhh);
    k_tw<<<256, 256>>>(projw);
    k_cp<<<Bn, 128>>>(projw);

    k_steps<<<NBLK, 256, SMEM_STEP>>>(projb, out);
    k_logits<<<128, 256>>>(Tn - 1, projb, out);
}

// round 13
// speedup vs baseline: 1.2214x; 1.0018x over previous
#include <cuda_runtime.h>
#include <cuda_fp16.h>
#include <math.h>

#define Bn 1024
#define Dn 512
#define Vn 128
#define Tn 201

// ---------------- device scratch ----------------
__device__ float  g_c[Bn * Dn];
__device__ float  g_ctx[Bn * Dn];
__device__ __half g_Ah[2][Bn * Dn];        // ping-pong hx hi-limb
__device__ __half g_Al[2][Bn * Dn];        // ping-pong hx lo-limb
__device__ __half g_Bh[4 * Dn * Dn];       // W_hh hi-limb [2048x512]
__device__ __half g_Bl[4 * Dn * Dn];       // W_hh lo-limb
__device__ __half g_Ph[Vn * Dn];           // proj_w hi-limb [128x512]
__device__ __half g_Pl[Vn * Dn];           // proj_w lo-limb
__device__ float  g_E2[Vn * 4 * Dn];       // embed @ W_ih^T + b_ih + b_hh
__device__ float  g_CP[Bn * Vn];           // ctx @ proj_w^T  (time-invariant)
__device__ int    g_token[Bn];
__device__ unsigned g_gcnt[8];             // per-group barrier arrive counts
__device__ unsigned g_ggen[8];             // per-group barrier generations
__device__ int    g_tokrdy[8];             // per-group token-ready step

__device__ __forceinline__ float sigexact(float x) {
    return 1.f / (1.f + expf(-x));
}
__device__ __forceinline__ void splitf(float x, __half& hi, __half& lo) {
    hi = __float2half_rn(x);
    lo = __float2half_rn(x - __half2float(hi));
}

// ---------------- mma / ldmatrix / cp.async wrappers ----------------
__device__ __forceinline__ void mma16816(float* c, const unsigned* a, const unsigned* b) {
    asm volatile(
        "mma.sync.aligned.m16n8k16.row.col.f32.f16.f16.f32 "
        "{%0,%1,%2,%3}, {%4,%5,%6,%7}, {%8,%9}, {%0,%1,%2,%3};"
        : "+f"(c[0]), "+f"(c[1]), "+f"(c[2]), "+f"(c[3])
        : "r"(a[0]), "r"(a[1]), "r"(a[2]), "r"(a[3]), "r"(b[0]), "r"(b[1]));
}
__device__ __forceinline__ void ldm4(unsigned* r, unsigned addr) {
    asm volatile("ldmatrix.sync.aligned.m8n8.x4.shared.b16 {%0,%1,%2,%3}, [%4];"
        : "=r"(r[0]), "=r"(r[1]), "=r"(r[2]), "=r"(r[3]) : "r"(addr));
}
__device__ __forceinline__ void cpasync16(unsigned dst, const void* src) {
    asm volatile("cp.async.ca.shared.global [%0], [%1], 16;" :: "r"(dst), "l"(src));
}
#define CP_COMMIT() asm volatile("cp.async.commit_group;")
#define CP_WAIT2()  asm volatile("cp.async.wait_group 2;")

// ---------------- P1: layernorm(h0) + attention context + init ----------------
__global__ void k_init(const float* __restrict__ fm, const float* __restrict__ pooled,
                       const float* __restrict__ gamma, const float* __restrict__ beta,
                       const float* __restrict__ attnw, const int* __restrict__ sos) {
    extern __shared__ float dyn[];
    float* sfm = dyn;            // 25088 floats
    float* swf = dyn + 25088;    // 512 floats
    __shared__ float red[256];
    __shared__ float saw[64];
    __shared__ float sstat[2];
    __shared__ float sh0[512];

    int b = blockIdx.x;
    int tid = threadIdx.x;

    const float4* fmb = (const float4*)(fm + (size_t)b * 25088);
    for (int i = tid; i < 6272; i += 256) ((float4*)sfm)[i] = fmb[i];
    for (int i = tid; i < 512; i += 256) swf[i] = attnw[i];

    float x0 = pooled[b * Dn + tid];
    float x1 = pooled[b * Dn + 256 + tid];
    red[tid] = x0 + x1;
    __syncthreads();
    for (int s = 128; s > 0; s >>= 1) {
        if (tid < s) red[tid] += red[tid + s];
        __syncthreads();
    }
    if (tid == 0) sstat[0] = red[0] * (1.0f / Dn);
    __syncthreads();
    float mu = sstat[0];
    float d0 = x0 - mu, d1 = x1 - mu;
    red[tid] = d0 * d0 + d1 * d1;
    __syncthreads();
    for (int s = 128; s > 0; s >>= 1) {
        if (tid < s) red[tid] += red[tid + s];
        __syncthreads();
    }
    if (tid == 0) sstat[1] = rsqrtf(red[0] * (1.0f / Dn) + 1e-5f);
    __syncthreads();
    float rs = sstat[1];
    sh0[tid]       = d0 * rs * gamma[tid]       + beta[tid];
    sh0[256 + tid] = d1 * rs * gamma[256 + tid] + beta[256 + tid];

    if (tid < 49) {
        float sc = 0.f;
        #pragma unroll 8
        for (int d = 0; d < 512; d++) sc += sfm[d * 49 + tid] * swf[d];
        saw[tid] = sc;
    }
    __syncthreads();
    if (tid == 0) {
        float mx = -1e30f;
        for (int p = 0; p < 49; p++) mx = fmaxf(mx, saw[p]);
        float sm = 0.f;
        for (int p = 0; p < 49; p++) { float e = expf(saw[p] - mx); saw[p] = e; sm += e; }
        sstat[0] = 1.0f / sm;
    }
    __syncthreads();
    float inv = sstat[0];

    for (int d = tid; d < 512; d += 256) {
        float acc = 0.f;
        #pragma unroll
        for (int p = 0; p < 49; p++) acc += saw[p] * sfm[d * 49 + p];
        float ctx = acc * inv;
        int idx = b * Dn + d;
        g_ctx[idx] = ctx;
        g_c[idx] = 0.f;
        float hx = ctx + sh0[d];
        __half hi, lo;
        splitf(hx, hi, lo);
        g_Ah[0][idx] = hi;
        g_Al[0][idx] = lo;
    }
    if (tid == 0) g_token[b] = *sos;
    if (b == 0 && tid < 8) { g_gcnt[tid] = 0; g_ggen[tid] = 0; g_tokrdy[tid] = 0; }
}

// ---------------- one-time: split W_hh / proj_w into f16 limbs ----------------
__global__ void k_splitW(const float* __restrict__ W) {
    int idx = blockIdx.x * 256 + threadIdx.x;   // 1048576 total
    float x = W[idx];
    __half hi, lo;
    splitf(x, hi, lo);
    g_Bh[idx] = hi;
    g_Bl[idx] = lo;
}
__global__ void k_splitP(const float* __restrict__ P) {
    int idx = blockIdx.x * 256 + threadIdx.x;   // 65536 total
    float x = P[idx];
    __half hi, lo;
    splitf(x, hi, lo);
    g_Ph[idx] = hi;
    g_Pl[idx] = lo;
}
// ---------------- one-time: CP = ctx @ proj_w^T ----------------
__global__ void k_cp(const float* __restrict__ projw) {
    __shared__ float sctx[512];
    int b = blockIdx.x;
    int tid = threadIdx.x;   // 128
    for (int i = tid; i < 512; i += 128) sctx[i] = g_ctx[b * Dn + i];
    __syncthreads();
    const float* P = projw + (size_t)tid * Dn;
    float acc = 0.f;
    #pragma unroll 8
    for (int k = 0; k < 512; k++) acc += sctx[k] * P[k];
    g_CP[b * Vn + tid] = acc;
}

// ---------------- E2 = embed @ W_ih^T + b_ih + b_hh (one-time) ----------------
__global__ __launch_bounds__(256) void k_e2(const float* __restrict__ emb,
                                            const float* __restrict__ Wih,
                                            const float* __restrict__ bih,
                                            const float* __restrict__ bhh) {
    __shared__ __align__(16) float sA[16 * 68];
    __shared__ __align__(16) float sB[16 * 68];
    int m0 = blockIdx.y * 64;
    int n0 = blockIdx.x * 64;
    int tid = threadIdx.x;
    int tx = tid & 15, ty = tid >> 4;
    int lm = tid >> 2;
    int lk = (tid & 3) * 4;
    const float* Ap = emb + (size_t)(m0 + lm) * Dn + lk;
    const float* Bp = Wih + (size_t)(n0 + lm) * Dn + lk;
    float acc[4][4] = {};
    for (int kt = 0; kt < 512; kt += 16) {
        float4 a = *(const float4*)(Ap + kt);
        float4 bb = *(const float4*)(Bp + kt);
        sA[(lk + 0) * 68 + lm] = a.x;  sA[(lk + 1) * 68 + lm] = a.y;
        sA[(lk + 2) * 68 + lm] = a.z;  sA[(lk + 3) * 68 + lm] = a.w;
        sB[(lk + 0) * 68 + lm] = bb.x; sB[(lk + 1) * 68 + lm] = bb.y;
        sB[(lk + 2) * 68 + lm] = bb.z; sB[(lk + 3) * 68 + lm] = bb.w;
        __syncthreads();
        #pragma unroll
        for (int k = 0; k < 16; k++) {
            float4 av = *(const float4*)&sA[k * 68 + ty * 4];
            float4 bv = *(const float4*)&sB[k * 68 + tx * 4];
            float ar[4] = {av.x, av.y, av.z, av.w};
            float br[4] = {bv.x, bv.y, bv.z, bv.w};
            #pragma unroll
            for (int i = 0; i < 4; i++)
                #pragma unroll
                for (int j = 0; j < 4; j++) acc[i][j] += ar[i] * br[j];
        }
        __syncthreads();
    }
    int gj0 = n0 + tx * 4;
    float4 b1 = *(const float4*)&bih[gj0];
    float4 b2 = *(const float4*)&bhh[gj0];
    #pragma unroll
    for (int i = 0; i < 4; i++) {
        int gv = m0 + ty * 4 + i;
        float4 o;
        o.x = acc[i][0] + b1.x + b2.x;
        o.y = acc[i][1] + b1.y + b2.y;
        o.z = acc[i][2] + b1.z + b2.z;
        o.w = acc[i][3] + b1.w + b2.w;
        *(float4*)&g_E2[(size_t)gv * 2048 + gj0] = o;
    }
}

// ---------------- PERSISTENT kernel: 8 independent groups of 17 blocks ---------
// Group m: blocks (m,0..15)=gates tiles, (m,16)=logits tile. Batch rows 128m..+127.
// k32 chunks (16 iters, 4 stages x 40KB), k-rotation rot=n: gates block's stage-0
// chunk is the hx slice ITS OWN epilogue wrote -> prefetched pre-barrier.
// Logits arrives at the group barrier right after argmax; out stores off-path.
#define ST_ROW 80
#define OFF_AH 0
#define OFF_AL 10240
#define OFF_BH 20480
#define OFF_BL 30720
#define STAGE_BYTES 40960
#define SMEM_STEP (STAGE_BYTES * 4)   // 160KB

__global__ __launch_bounds__(256, 1) void k_steps(const float* __restrict__ projb,
                                                  float* __restrict__ out) {
    extern __shared__ char sdyn[];
    int bid = blockIdx.x;
    int tid = threadIdx.x;
    int lane = tid & 31;
    int wid = tid >> 5;

    int n = bid % 17;            // 0..16
    int m = bid / 17;            // 0..7
    bool isLog = (n == 16);
    int d0 = n * 32;             // gates tiles only
    int bm0 = m * 128;
    int m0w = (wid >> 2) * 64;
    int wn = wid & 3;
    int rot = isLog ? 0 : n;     // k32-chunk rotation

    unsigned sb = (unsigned)__cvta_generic_to_shared(sdyn);

    // ldmatrix lane base addresses (stage-relative; +32 bytes for k16-half 1)
    unsigned aAH[4], aAL[4], bAH[2], bAL[2];
    #pragma unroll
    for (int mi = 0; mi < 4; mi++) {
        int row = m0w + mi * 16 + ((lane >> 3) & 1) * 8 + (lane & 7);
        unsigned off = (unsigned)(row * ST_ROW + ((lane >> 4) & 1) * 16);
        aAH[mi] = sb + OFF_AH + off;
        aAL[mi] = sb + OFF_AL + off;
    }
    #pragma unroll
    for (int pi = 0; pi < 2; pi++) {
        int row = wn * 32 + pi * 16 + ((lane >> 4) & 1) * 8 + (lane & 7);
        unsigned off = (unsigned)(row * ST_ROW + ((lane >> 3) & 1) * 16);
        bAH[pi] = sb + OFF_BH + off;
        bAL[pi] = sb + OFF_BL + off;
    }

    // staging: thread -> (row, 32B-half of the 64B chunk-row)
    int srow = tid >> 1, shalf = tid & 1;
    unsigned stOff = (unsigned)(srow * ST_ROW + shalf * 32);
    int grow = isLog ? srow
                     : ((srow >> 3) & 3) * 512 + d0 + (srow >> 5) * 8 + (srow & 7);
    const __half* BhS = isLog ? g_Ph : g_Bh;
    const __half* BlS = isLog ? g_Pl : g_Bl;
    const char* pBh = (const char*)(BhS + (size_t)grow * Dn) + shalf * 32;
    const char* pBl = (const char*)(BlS + (size_t)grow * Dn) + shalf * 32;
    size_t aByteOff = (size_t)(bm0 + srow) * Dn * 2 + shalf * 32;

#define LDA(st, kc, pAh_, pAl_) do {                                            \
        unsigned _d = sb + (unsigned)(st) * STAGE_BYTES + stOff;                \
        const char* _s1 = (pAh_) + (kc) * 64;                                   \
        const char* _s2 = (pAl_) + (kc) * 64;                                   \
        cpasync16(_d + OFF_AH, _s1); cpasync16(_d + OFF_AH + 16, _s1 + 16);     \
        cpasync16(_d + OFF_AL, _s2); cpasync16(_d + OFF_AL + 16, _s2 + 16);     \
    } while (0)
#define LDB(st, kc) do {                                                        \
        unsigned _d = sb + (unsigned)(st) * STAGE_BYTES + stOff;                \
        const char* _s1 = pBh + (kc) * 64;                                      \
        const char* _s2 = pBl + (kc) * 64;                                      \
        cpasync16(_d + OFF_BH, _s1); cpasync16(_d + OFF_BH + 16, _s1 + 16);     \
        cpasync16(_d + OFF_BL, _s2); cpasync16(_d + OFF_BL + 16, _s2 + 16);     \
    } while (0)

    // prologue: B chunks rot..rot+2 into stages 0..2; gates also self A chunk rot
    LDB(0, rot); LDB(1, (rot + 1) & 15); LDB(2, (rot + 2) & 15);
    if (!isLog) {
        const char* pAh0 = (const char*)(g_Ah[0]) + aByteOff;
        const char* pAl0 = (const char*)(g_Al[0]) + aByteOff;
        LDA(0, rot, pAh0, pAl0);
    }
    CP_COMMIT();   // gX

    for (int t = 0; t <= Tn; t++) {
        if (t == Tn && !isLog) break;          // groups' gates finish after Tn-1

        int par = t & 1;
        const char* pAh = (const char*)(g_Ah[par]) + aByteOff;
        const char* pAl = (const char*)(g_Al[par]) + aByteOff;

        // post-barrier A issues (foreign chunks; logits also stage 0)
        if (isLog) { LDA(0, rot, pAh, pAl); CP_COMMIT(); }
        LDA(1, (rot + 1) & 15, pAh, pAl); CP_COMMIT();
        LDA(2, (rot + 2) & 15, pAh, pAl); CP_COMMIT();

        float c[4][4][4];
        #pragma unroll
        for (int mi = 0; mi < 4; mi++)
            #pragma unroll
            for (int ni = 0; ni < 4; ni++)
                #pragma unroll
                for (int q = 0; q < 4; q++) c[mi][ni][q] = 0.f;

        for (int kt = 0; kt < 16; kt++) {
            CP_WAIT2();
            __syncthreads();
            unsigned so = (unsigned)((kt & 3) * STAGE_BYTES);

            if (kt + 3 < 16) {
                int kc = (rot + kt + 3) & 15;
                int st = (kt + 3) & 3;
                LDA(st, kc, pAh, pAl);
                LDB(st, kc);
            }
            CP_COMMIT();

            #pragma unroll
            for (int h = 0; h < 2; h++) {
                unsigned ho = so + (unsigned)(h * 32);
                unsigned AH[4][4], AL[4][4], BH[2][4], BL[2][4];
                #pragma unroll
                for (int mi = 0; mi < 4; mi++) { ldm4(AH[mi], aAH[mi] + ho); ldm4(AL[mi], aAL[mi] + ho); }
                #pragma unroll
                for (int pi = 0; pi < 2; pi++) { ldm4(BH[pi], bAH[pi] + ho); ldm4(BL[pi], bAL[pi] + ho); }

                #pragma unroll
                for (int mi = 0; mi < 4; mi++)
                    #pragma unroll
                    for (int ni = 0; ni < 4; ni++)
                        mma16816(c[mi][ni], AH[mi], &BH[ni >> 1][(ni & 1) * 2]);
                #pragma unroll
                for (int mi = 0; mi < 4; mi++)
                    #pragma unroll
                    for (int ni = 0; ni < 4; ni++)
                        mma16816(c[mi][ni], AH[mi], &BL[ni >> 1][(ni & 1) * 2]);
                #pragma unroll
                for (int mi = 0; mi < 4; mi++)
                    #pragma unroll
                    for (int ni = 0; ni < 4; ni++)
                        mma16816(c[mi][ni], AL[mi], &BH[ni >> 1][(ni & 1) * 2]);
            }
        }

        int g = lane >> 2, tg = lane & 3;

        if (isLog) {
            // ============ LOGITS(t-1) epilogue ============
            if (t > 0) {
                int ts = t - 1;
                float* sL = (float*)sdyn;          // 128 x 132 (over stages 0-1)

                #pragma unroll
                for (int mi = 0; mi < 4; mi++) {
                    #pragma unroll
                    for (int ni = 0; ni < 4; ni++) {
                        int v0 = wn * 32 + ni * 8 + tg * 2;
                        float2 pb = *(const float2*)&projb[v0];
                        #pragma unroll
                        for (int q = 0; q < 2; q++) {
                            int lrow = m0w + mi * 16 + g + q * 8;
                            int row = bm0 + lrow;
                            float2 cp = *(const float2*)&g_CP[row * Vn + v0];
                            float lg0 = c[mi][ni][q * 2 + 0] - cp.x + pb.x;
                            float lg1 = c[mi][ni][q * 2 + 1] - cp.y + pb.y;
                            *(float2*)&sL[lrow * 132 + v0] = make_float2(lg0, lg1);
                        }
                    }
                }
                __syncthreads();

                // argmax (token critical path), then release + EARLY barrier arrive
                for (int r = 0; r < 16; r++) {
                    int lrow = wid * 16 + r;
                    float best = sL[lrow * 132 + lane];
                    int bi = lane;
                    #pragma unroll
                    for (int off = 32; off < 128; off += 32) {
                        float vv = sL[lrow * 132 + lane + off];
                        if (vv > best) { best = vv; bi = lane + off; }
                    }
                    #pragma unroll
                    for (int s = 16; s > 0; s >>= 1) {
                        float ov = __shfl_down_sync(0xffffffffu, best, s);
                        int oi = __shfl_down_sync(0xffffffffu, bi, s);
                        if (ov > best || (ov == best && oi < bi)) { best = ov; bi = oi; }
                    }
                    if (lane == 0) g_token[bm0 + lrow] = bi;
                }
                __syncthreads();
                if (tid == 0 && t < Tn) {
                    __threadfence();
                    *(volatile int*)&g_tokrdy[m] = t;
                    unsigned old = atomicAdd(&g_gcnt[m], 1);          // early arrive
                    if (old == 16) {
                        g_gcnt[m] = 0;
                        __threadfence();
                        *(volatile unsigned*)&g_ggen[m] = (unsigned)(t + 1);
                    }
                }

                // deferred out stores (off all critical paths)
                for (int i = tid; i < 128 * 128; i += 256) {
                    int lr = i >> 7, v = i & 127;
                    out[(size_t)(bm0 + lr) * (Vn * Tn) + (size_t)v * Tn + ts] =
                        sL[lr * 132 + v];
                }
                if (t == Tn) break;                // final logits done
                __syncthreads();                   // sL reads done before B refill
            } else {
                // t == 0: no logits yet; just arrive
                __threadfence();
                __syncthreads();
                if (tid == 0) {
                    unsigned old = atomicAdd(&g_gcnt[m], 1);
                    if (old == 16) {
                        g_gcnt[m] = 0;
                        __threadfence();
                        *(volatile unsigned*)&g_ggen[m] = 1u;
                    }
                }
            }
            // B refill for next iteration, then wait for group
            LDB(0, rot); LDB(1, (rot + 1) & 15); LDB(2, (rot + 2) & 15);
            CP_COMMIT();   // gX
            if (tid == 0) {
                while (*(volatile unsigned*)&g_ggen[m] < (unsigned)(t + 1)) {}
                __threadfence();
            }
            __syncthreads();
        } else {
            // ============ GATES(t) epilogue ============
            // B refill first (static data) — overlaps the token wait
            LDB(0, rot); LDB(1, (rot + 1) & 15); LDB(2, (rot + 2) & 15);

            if (tid == 0) {
                while (*(volatile int*)&g_tokrdy[m] < t) {}
                __threadfence();
            }
            __syncthreads();

            __half* AhO = g_Ah[par ^ 1];
            __half* AlO = g_Al[par ^ 1];
            int ddb = wn * 8 + tg * 2;
            #pragma unroll
            for (int mi = 0; mi < 4; mi++) {
                #pragma unroll
                for (int q = 0; q < 2; q++) {
                    int row = bm0 + m0w + mi * 16 + g + q * 8;
                    int tok = g_token[row];
                    const float* E = g_E2 + (size_t)tok * 2048 + d0 + ddb;
                    float2 ei = *(const float2*)(E);
                    float2 ef = *(const float2*)(E + 512);
                    float2 eg = *(const float2*)(E + 1024);
                    float2 eo = *(const float2*)(E + 1536);
                    int idx = row * Dn + d0 + ddb;
                    float2 cold = *(const float2*)&g_c[idx];
                    float2 ctx = *(const float2*)&g_ctx[idx];

                    float gi = c[mi][0][q * 2 + 0] + ei.x;
                    float gf = c[mi][1][q * 2 + 0] + ef.x;
                    float gg = c[mi][2][q * 2 + 0] + eg.x;
                    float go = c[mi][3][q * 2 + 0] + eo.x;
                    float cn0 = sigexact(gf) * cold.x + sigexact(gi) * tanhf(gg);
                    float hn0 = sigexact(go) * tanhf(cn0);

                    gi = c[mi][0][q * 2 + 1] + ei.y;
                    gf = c[mi][1][q * 2 + 1] + ef.y;
                    gg = c[mi][2][q * 2 + 1] + eg.y;
                    go = c[mi][3][q * 2 + 1] + eo.y;
                    float cn1 = sigexact(gf) * cold.y + sigexact(gi) * tanhf(gg);
                    float hn1 = sigexact(go) * tanhf(cn1);

                    *(float2*)&g_c[idx] = make_float2(cn0, cn1);
                    float hx0 = hn0 + ctx.x;
                    float hx1 = hn1 + ctx.y;
                    __half h0h, h0l, h1h, h1l;
                    splitf(hx0, h0h, h0l);
                    splitf(hx1, h1h, h1l);
                    *(__half2*)&AhO[idx] = __halves2half2(h0h, h1h);
                    *(__half2*)&AlO[idx] = __halves2half2(h0l, h1l);
                }
            }
            __syncthreads();       // hx stores visible block-wide (self A prefetch)

            // self-chunk A prefetch for next iteration (chunk rot = own columns)
            {
                const char* pAhN = (const char*)(g_Ah[par ^ 1]) + aByteOff;
                const char* pAlN = (const char*)(g_Al[par ^ 1]) + aByteOff;
                LDA(0, rot, pAhN, pAlN);
            }
            CP_COMMIT();   // gX = {B0,B1,B2,A0}

            // group barrier (arrive + wait)
            __threadfence();
            __syncthreads();
            if (tid == 0) {
                unsigned old = atomicAdd(&g_gcnt[m], 1);
                if (old == 16) {
                    g_gcnt[m] = 0;
                    __threadfence();
                    *(volatile unsigned*)&g_ggen[m] = (unsigned)(t + 1);
                } else {
                    while (*(volatile unsigned*)&g_ggen[m] < (unsigned)(t + 1)) {}
                    __threadfence();
                }
            }
            __syncthreads();
        }
    }
#undef LDA
#undef LDB
}

// ---------------- launch ----------------
extern "C" void kernel_launch(void* const* d_in, const int* in_sizes, int n_in,
                              void* d_out, int out_size) {
    const float* fm     = (const float*)d_in[0];
    const float* pooled = (const float*)d_in[1];
    const float* gamma  = (const float*)d_in[2];
    const float* beta   = (const float*)d_in[3];
    const float* Wih    = (const float*)d_in[4];
    const float* Whh    = (const float*)d_in[5];
    const float* bih    = (const float*)d_in[6];
    const float* bhh    = (const float*)d_in[7];
    const float* emb    = (const float*)d_in[8];
    const float* attnw  = (const float*)d_in[9];
    // d_in[10] = attn_b: cancels in softmax (constant over the axis)
    const float* projw  = (const float*)d_in[11];
    const float* projb  = (const float*)d_in[12];
    const int*   sos    = (const int*)d_in[13];
    float* out = (float*)d_out;

    const int dynBytes = (25088 + 512) * 4;
    cudaFuncSetAttribute(k_init, cudaFuncAttributeMaxDynamicSharedMemorySize, dynBytes);
    cudaFuncSetAttribute(k_steps, cudaFuncAttributeMaxDynamicSharedMemorySize, SMEM_STEP);

    k_init<<<Bn, 256, dynBytes>>>(fm, pooled, gamma, beta, attnw, sos);
    k_splitW<<<4096, 256>>>(Whh);
    k_splitP<<<256, 256>>>(projw);
    k_e2<<<dim3(32, 2), 256>>>(emb, Wih, bih, bhh);
    k_cp<<<Bn, 128>>>(projw);

    k_steps<<<136, 256, SMEM_STEP>>>(projb, out);
}